// round 10
// baseline (speedup 1.0000x reference)
#include <cuda_runtime.h>
#include <math_constants.h>

#define NN 50000
#define EE 800000
#define HH 4
#define CC 64
#define DE 16
#define GG 64
#define HC 256   // H*C
#define NEG_SLOPE 0.2f
#define GN_EPS 1e-5f

// ---------------- device scratch (no allocations allowed) ----------------
__device__ float g_x[NN * HC];      // projected node features [N, H*C]  (51.2 MB)
__device__ float g_asrc[NN * HH];   // per-node src attention logits
__device__ float g_adst[NN * HH];   // per-node dst attention logits
__device__ float g_amax[NN * HH];   // segment max per (dst, h)
__device__ float g_denom[NN * HH];  // segment sum of exp per (dst, h)
__device__ float g_vedge[DE * HH];  // folded W_edge @ att_edge, layout [d][h]

// ---------------- helpers ----------------
__device__ __forceinline__ void atomicMaxFloat(float* addr, float value) {
    if (value >= 0.0f) {
        atomicMax((int*)addr, __float_as_int(value));
    } else {
        atomicMin((unsigned int*)addr, __float_as_uint(value));
    }
}

// ---------------- kernels ----------------

// Zero the y output region; init softmax tables.
__global__ void k_init(float* __restrict__ outy) {
    int i = blockIdx.x * blockDim.x + threadIdx.x;
    int stride = gridDim.x * blockDim.x;
    for (int j = i; j < NN * CC; j += stride) outy[j] = 0.0f;
    for (int j = i; j < NN * HH; j += stride) {
        g_amax[j] = -CUDART_INF_F;
        g_denom[j] = 0.0f;
    }
}

// v[d][h] = sum_c W_edge[d, h*C + c] * att_edge[h, c]   (tiny: 16x4)
__global__ void k_vedge(const float* __restrict__ We, const float* __restrict__ ae) {
    int t = threadIdx.x;           // 64 threads
    int d = t >> 2, h = t & 3;
    float s = 0.0f;
    #pragma unroll 16
    for (int c = 0; c < CC; c++)
        s = fmaf(We[d * HC + h * CC + c], ae[h * CC + c], s);
    g_vedge[d * HH + h] = s;
}

// x = node @ W  : block handles ROWS node rows x 256 output cols.
#define PROJ_ROWS 16
__global__ void k_proj(const float* __restrict__ node, const float* __restrict__ W) {
    __shared__ float sn[PROJ_ROWS][CC];
    int block0 = blockIdx.x * PROJ_ROWS;
    int tid = threadIdx.x;  // 256
    for (int i = tid; i < PROJ_ROWS * CC; i += 256) {
        int r = i >> 6, c = i & 63;
        int n = block0 + r;
        sn[r][c] = (n < NN) ? node[n * CC + c] : 0.0f;
    }
    __syncthreads();
    float acc[PROJ_ROWS];
    #pragma unroll
    for (int r = 0; r < PROJ_ROWS; r++) acc[r] = 0.0f;
    #pragma unroll 4
    for (int k = 0; k < CC; k++) {
        float wk = W[k * HC + tid];
        #pragma unroll
        for (int r = 0; r < PROJ_ROWS; r++) acc[r] = fmaf(sn[r][k], wk, acc[r]);
    }
    #pragma unroll
    for (int r = 0; r < PROJ_ROWS; r++) {
        int n = block0 + r;
        if (n < NN) g_x[n * HC + tid] = acc[r];
    }
}

// a_src[n,h], a_dst[n,h]: one warp per (n,h).
__global__ void k_attnodes(const float* __restrict__ att_src,
                           const float* __restrict__ att_dst) {
    int gw = (blockIdx.x * blockDim.x + threadIdx.x) >> 5;
    int lane = threadIdx.x & 31;
    if (gw >= NN * HH) return;
    int n = gw >> 2, h = gw & 3;
    float2 xv = ((const float2*)(g_x + n * HC + h * CC))[lane];
    float2 as = ((const float2*)(att_src + h * CC))[lane];
    float2 ad = ((const float2*)(att_dst + h * CC))[lane];
    float s = xv.x * as.x + xv.y * as.y;
    float d = xv.x * ad.x + xv.y * ad.y;
    #pragma unroll
    for (int o = 16; o > 0; o >>= 1) {
        s += __shfl_xor_sync(0xffffffffu, s, o);
        d += __shfl_xor_sync(0xffffffffu, d, o);
    }
    if (lane == 0) { g_asrc[gw] = s; g_adst[gw] = d; }
}

// Pass A: alpha = lrelu(a_src[src]+a_dst[dst]+edge_attr@v); store; atomicMax per (dst,h).
__global__ void k_edgeA(const int* __restrict__ ei,
                        const float* __restrict__ edge_attr,
                        float* __restrict__ att) {
    __shared__ float sv[DE * HH];
    if (threadIdx.x < DE * HH) sv[threadIdx.x] = g_vedge[threadIdx.x];
    __syncthreads();
    int e = blockIdx.x * blockDim.x + threadIdx.x;
    if (e >= EE) return;
    const float4* ea = (const float4*)(edge_attr + (size_t)e * DE);
    float aeh[HH] = {0.f, 0.f, 0.f, 0.f};
    #pragma unroll
    for (int q = 0; q < 4; q++) {
        float4 t = ea[q];
        #pragma unroll
        for (int h = 0; h < HH; h++) {
            aeh[h] += t.x * sv[(q * 4 + 0) * HH + h]
                    + t.y * sv[(q * 4 + 1) * HH + h]
                    + t.z * sv[(q * 4 + 2) * HH + h]
                    + t.w * sv[(q * 4 + 3) * HH + h];
        }
    }
    int src = ei[e], dst = ei[EE + e];
    float4 al4;
    float* al = (float*)&al4;
    #pragma unroll
    for (int h = 0; h < HH; h++) {
        float a = g_asrc[src * HH + h] + g_adst[dst * HH + h] + aeh[h];
        a = (a > 0.0f) ? a : NEG_SLOPE * a;
        al[h] = a;
        atomicMaxFloat(&g_amax[dst * HH + h], a);
    }
    *(float4*)(att + (size_t)e * HH) = al4;
}

// Pass B: ex = exp(alpha - amax[dst]); store in place; atomicAdd denom.
__global__ void k_edgeB(const int* __restrict__ ei, float* __restrict__ att) {
    int e = blockIdx.x * blockDim.x + threadIdx.x;
    if (e >= EE) return;
    int dst = ei[EE + e];
    float4 al = *(float4*)(att + (size_t)e * HH);
    float4 mx = *(const float4*)(g_amax + dst * HH);
    float e0 = __expf(al.x - mx.x);
    float e1 = __expf(al.y - mx.y);
    float e2 = __expf(al.z - mx.z);
    float e3 = __expf(al.w - mx.w);
    *(float4*)(att + (size_t)e * HH) = make_float4(e0, e1, e2, e3);
    atomicAdd(&g_denom[dst * HH + 0], e0);
    atomicAdd(&g_denom[dst * HH + 1], e1);
    atomicAdd(&g_denom[dst * HH + 2], e2);
    atomicAdd(&g_denom[dst * HH + 3], e3);
}

// Pass C: att = ex/denom (write output), scatter head-summed message into out[N,C].
// One warp per edge; lane handles 2 channels.
__global__ void k_edgeC(const int* __restrict__ ei,
                        float* __restrict__ att,
                        float* __restrict__ outy) {
    int e = (blockIdx.x * blockDim.x + threadIdx.x) >> 5;
    int lane = threadIdx.x & 31;
    if (e >= EE) return;
    int src = ei[e], dst = ei[EE + e];
    float4 ex = *(const float4*)(att + (size_t)e * HH);
    float4 dn = *(const float4*)(g_denom + dst * HH);
    float a0 = ex.x / (dn.x + 1e-16f);
    float a1 = ex.y / (dn.y + 1e-16f);
    float a2 = ex.z / (dn.z + 1e-16f);
    float a3 = ex.w / (dn.w + 1e-16f);
    if (lane == 0)
        *(float4*)(att + (size_t)e * HH) = make_float4(a0, a1, a2, a3);
    const float2* xr = (const float2*)(g_x + (size_t)src * HC);
    float2 v;
    float acc0, acc1;
    v = xr[0 * 32 + lane]; acc0 = a0 * v.x;             acc1 = a0 * v.y;
    v = xr[1 * 32 + lane]; acc0 = fmaf(a1, v.x, acc0);  acc1 = fmaf(a1, v.y, acc1);
    v = xr[2 * 32 + lane]; acc0 = fmaf(a2, v.x, acc0);  acc1 = fmaf(a2, v.y, acc1);
    v = xr[3 * 32 + lane]; acc0 = fmaf(a3, v.x, acc0);  acc1 = fmaf(a3, v.y, acc1);
    atomicAdd(&outy[dst * CC + lane * 2 + 0], acc0);
    atomicAdd(&outy[dst * CC + lane * 2 + 1], acc1);
}

// GraphNorm: one block per group (batch_ptr sorted -> contiguous node ranges).
// t = out_raw/H + bias; mean/var per (group,channel); y = relu(w*(t-mean*sc)*rstd + b2).
__global__ void k_gn(const int* __restrict__ batch_ptr,
                     const float* __restrict__ bias,
                     const float* __restrict__ gnw,
                     const float* __restrict__ gnb,
                     const float* __restrict__ gnsc,
                     float* __restrict__ outy) {
    int g = blockIdx.x;
    __shared__ int s_lo, s_hi;
    if (threadIdx.x == 0) {
        int lo = 0, hi = NN;
        while (lo < hi) { int m = (lo + hi) >> 1; if (batch_ptr[m] < g) lo = m + 1; else hi = m; }
        s_lo = lo;
        int lo2 = lo, hi2 = NN;
        while (lo2 < hi2) { int m = (lo2 + hi2) >> 1; if (batch_ptr[m] < g + 1) lo2 = m + 1; else hi2 = m; }
        s_hi = lo2;
    }
    __syncthreads();
    int lo = s_lo, hi = s_hi;
    float cnt = (float)max(hi - lo, 1);
    int ch = threadIdx.x & 63;
    int ro = threadIdx.x >> 6;  // 0..3
    float b = bias[ch], w = gnw[ch], gb = gnb[ch], sc = gnsc[ch];
    __shared__ float red[256];
    __shared__ float s_ms[64], s_rs[64];

    // phase 1: mean
    float s = 0.0f;
    for (int r = lo + ro; r < hi; r += 4) s += outy[r * CC + ch];
    red[threadIdx.x] = s;
    __syncthreads();
    if (threadIdx.x < 64) {
        float m = red[threadIdx.x] + red[threadIdx.x + 64] + red[threadIdx.x + 128] + red[threadIdx.x + 192];
        float mean = 0.25f * m / cnt + b;   // mean of (raw/4 + bias)
        s_ms[threadIdx.x] = mean * sc;
    }
    __syncthreads();
    float ms = s_ms[ch];

    // phase 2: var
    s = 0.0f;
    for (int r = lo + ro; r < hi; r += 4) {
        float t = fmaf(outy[r * CC + ch], 0.25f, b) - ms;
        s += t * t;
    }
    red[threadIdx.x] = s;
    __syncthreads();
    if (threadIdx.x < 64) {
        float v = (red[threadIdx.x] + red[threadIdx.x + 64] + red[threadIdx.x + 128] + red[threadIdx.x + 192]) / cnt;
        s_rs[threadIdx.x] = rsqrtf(v + GN_EPS);
    }
    __syncthreads();
    float rs = s_rs[ch];

    // phase 3: normalize + affine + relu (in place)
    for (int r = lo + ro; r < hi; r += 4) {
        float t = (fmaf(outy[r * CC + ch], 0.25f, b) - ms) * rs;
        float y = fmaf(w, t, gb);
        outy[r * CC + ch] = fmaxf(y, 0.0f);
    }
}

// ---------------- launch ----------------
extern "C" void kernel_launch(void* const* d_in, const int* in_sizes, int n_in,
                              void* d_out, int out_size) {
    const float* node      = (const float*)d_in[0];
    const int*   ei        = (const int*)d_in[1];
    const float* edge_attr = (const float*)d_in[2];
    const int*   batch_ptr = (const int*)d_in[3];
    const float* W         = (const float*)d_in[4];
    const float* W_edge    = (const float*)d_in[5];
    const float* att_src   = (const float*)d_in[6];
    const float* att_dst   = (const float*)d_in[7];
    const float* att_edge  = (const float*)d_in[8];
    const float* bias      = (const float*)d_in[9];
    const float* gnw       = (const float*)d_in[10];
    const float* gnb       = (const float*)d_in[11];
    const float* gnsc      = (const float*)d_in[12];

    float* outy = (float*)d_out;               // y region [N*C]
    float* att  = (float*)d_out + (size_t)NN * CC;  // att region [E*H]

    k_init<<<1024, 256>>>(outy);
    k_vedge<<<1, 64>>>(W_edge, att_edge);
    k_proj<<<(NN + PROJ_ROWS - 1) / PROJ_ROWS, 256>>>(node, W);
    k_attnodes<<<(NN * HH + 7) / 8, 256>>>(att_src, att_dst);
    k_edgeA<<<(EE + 255) / 256, 256>>>(ei, edge_attr, att);
    k_edgeB<<<(EE + 255) / 256, 256>>>(ei, att);
    k_edgeC<<<(EE + 7) / 8, 256>>>(ei, att, outy);
    k_gn<<<GG, 256>>>(batch_ptr, bias, gnw, gnb, gnsc, outy);
}

// round 11
// speedup vs baseline: 1.0022x; 1.0022x over previous
#include <cuda_runtime.h>
#include <math_constants.h>

#define NN 50000
#define EE 800000
#define HH 4
#define CC 64
#define DE 16
#define GG 64
#define HC 256   // H*C
#define NEG_SLOPE 0.2f
#define GN_EPS 1e-5f

// ---------------- device scratch (no allocations allowed) ----------------
__device__ float g_x[NN * HC];      // projected node features [N, H*C]  (51.2 MB)
__device__ float g_asrc[NN * HH];   // per-node src attention logits
__device__ float g_adst[NN * HH];   // per-node dst attention logits
__device__ float g_amax[NN * HH];   // segment max per (dst, h)
__device__ float g_denom[NN * HH];  // segment sum of exp per (dst, h)
__device__ float g_vedge[DE * HH];  // folded W_edge @ att_edge, layout [d][h]

// ---------------- helpers ----------------
__device__ __forceinline__ void atomicMaxFloat(float* addr, float value) {
    if (value >= 0.0f) {
        atomicMax((int*)addr, __float_as_int(value));
    } else {
        atomicMin((unsigned int*)addr, __float_as_uint(value));
    }
}

// ---------------- kernels ----------------

// Zero the y output region; init softmax tables.
__global__ void k_init(float* __restrict__ outy) {
    int i = blockIdx.x * blockDim.x + threadIdx.x;
    int stride = gridDim.x * blockDim.x;
    for (int j = i; j < NN * CC; j += stride) outy[j] = 0.0f;
    for (int j = i; j < NN * HH; j += stride) {
        g_amax[j] = -CUDART_INF_F;
        g_denom[j] = 0.0f;
    }
}

// v[d][h] = sum_c W_edge[d, h*C + c] * att_edge[h, c]   (tiny: 16x4)
__global__ void k_vedge(const float* __restrict__ We, const float* __restrict__ ae) {
    int t = threadIdx.x;           // 64 threads
    int d = t >> 2, h = t & 3;
    float s = 0.0f;
    #pragma unroll 16
    for (int c = 0; c < CC; c++)
        s = fmaf(We[d * HC + h * CC + c], ae[h * CC + c], s);
    g_vedge[d * HH + h] = s;
}

// x = node @ W  : block handles ROWS node rows x 256 output cols.
#define PROJ_ROWS 16
__global__ void k_proj(const float* __restrict__ node, const float* __restrict__ W) {
    __shared__ float sn[PROJ_ROWS][CC];
    int block0 = blockIdx.x * PROJ_ROWS;
    int tid = threadIdx.x;  // 256
    for (int i = tid; i < PROJ_ROWS * CC; i += 256) {
        int r = i >> 6, c = i & 63;
        int n = block0 + r;
        sn[r][c] = (n < NN) ? node[n * CC + c] : 0.0f;
    }
    __syncthreads();
    float acc[PROJ_ROWS];
    #pragma unroll
    for (int r = 0; r < PROJ_ROWS; r++) acc[r] = 0.0f;
    #pragma unroll 4
    for (int k = 0; k < CC; k++) {
        float wk = W[k * HC + tid];
        #pragma unroll
        for (int r = 0; r < PROJ_ROWS; r++) acc[r] = fmaf(sn[r][k], wk, acc[r]);
    }
    #pragma unroll
    for (int r = 0; r < PROJ_ROWS; r++) {
        int n = block0 + r;
        if (n < NN) g_x[n * HC + tid] = acc[r];
    }
}

// a_src[n,h], a_dst[n,h]: one warp per (n,h).
__global__ void k_attnodes(const float* __restrict__ att_src,
                           const float* __restrict__ att_dst) {
    int gw = (blockIdx.x * blockDim.x + threadIdx.x) >> 5;
    int lane = threadIdx.x & 31;
    if (gw >= NN * HH) return;
    int n = gw >> 2, h = gw & 3;
    float2 xv = ((const float2*)(g_x + n * HC + h * CC))[lane];
    float2 as = ((const float2*)(att_src + h * CC))[lane];
    float2 ad = ((const float2*)(att_dst + h * CC))[lane];
    float s = xv.x * as.x + xv.y * as.y;
    float d = xv.x * ad.x + xv.y * ad.y;
    #pragma unroll
    for (int o = 16; o > 0; o >>= 1) {
        s += __shfl_xor_sync(0xffffffffu, s, o);
        d += __shfl_xor_sync(0xffffffffu, d, o);
    }
    if (lane == 0) { g_asrc[gw] = s; g_adst[gw] = d; }
}

// Pass A: alpha = lrelu(a_src[src]+a_dst[dst]+edge_attr@v); store; atomicMax per (dst,h).
__global__ void k_edgeA(const int* __restrict__ ei,
                        const float* __restrict__ edge_attr,
                        float* __restrict__ att) {
    __shared__ float sv[DE * HH];
    if (threadIdx.x < DE * HH) sv[threadIdx.x] = g_vedge[threadIdx.x];
    __syncthreads();
    int e = blockIdx.x * blockDim.x + threadIdx.x;
    if (e >= EE) return;
    const float4* ea = (const float4*)(edge_attr + (size_t)e * DE);
    float aeh[HH] = {0.f, 0.f, 0.f, 0.f};
    #pragma unroll
    for (int q = 0; q < 4; q++) {
        float4 t = ea[q];
        #pragma unroll
        for (int h = 0; h < HH; h++) {
            aeh[h] += t.x * sv[(q * 4 + 0) * HH + h]
                    + t.y * sv[(q * 4 + 1) * HH + h]
                    + t.z * sv[(q * 4 + 2) * HH + h]
                    + t.w * sv[(q * 4 + 3) * HH + h];
        }
    }
    int src = ei[e], dst = ei[EE + e];
    float4 al4;
    float* al = (float*)&al4;
    #pragma unroll
    for (int h = 0; h < HH; h++) {
        float a = g_asrc[src * HH + h] + g_adst[dst * HH + h] + aeh[h];
        a = (a > 0.0f) ? a : NEG_SLOPE * a;
        al[h] = a;
        atomicMaxFloat(&g_amax[dst * HH + h], a);
    }
    *(float4*)(att + (size_t)e * HH) = al4;
}

// Pass B: ex = exp(alpha - amax[dst]); store in place; atomicAdd denom.
__global__ void k_edgeB(const int* __restrict__ ei, float* __restrict__ att) {
    int e = blockIdx.x * blockDim.x + threadIdx.x;
    if (e >= EE) return;
    int dst = ei[EE + e];
    float4 al = *(float4*)(att + (size_t)e * HH);
    float4 mx = *(const float4*)(g_amax + dst * HH);
    float e0 = __expf(al.x - mx.x);
    float e1 = __expf(al.y - mx.y);
    float e2 = __expf(al.z - mx.z);
    float e3 = __expf(al.w - mx.w);
    *(float4*)(att + (size_t)e * HH) = make_float4(e0, e1, e2, e3);
    atomicAdd(&g_denom[dst * HH + 0], e0);
    atomicAdd(&g_denom[dst * HH + 1], e1);
    atomicAdd(&g_denom[dst * HH + 2], e2);
    atomicAdd(&g_denom[dst * HH + 3], e3);
}

// Pass C: att = ex/denom (write output), scatter head-summed message into out[N,C].
// One warp per edge; lane handles 2 channels.
__global__ void k_edgeC(const int* __restrict__ ei,
                        float* __restrict__ att,
                        float* __restrict__ outy) {
    int e = (blockIdx.x * blockDim.x + threadIdx.x) >> 5;
    int lane = threadIdx.x & 31;
    if (e >= EE) return;
    int src = ei[e], dst = ei[EE + e];
    float4 ex = *(const float4*)(att + (size_t)e * HH);
    float4 dn = *(const float4*)(g_denom + dst * HH);
    float a0 = ex.x / (dn.x + 1e-16f);
    float a1 = ex.y / (dn.y + 1e-16f);
    float a2 = ex.z / (dn.z + 1e-16f);
    float a3 = ex.w / (dn.w + 1e-16f);
    if (lane == 0)
        *(float4*)(att + (size_t)e * HH) = make_float4(a0, a1, a2, a3);
    const float2* xr = (const float2*)(g_x + (size_t)src * HC);
    float2 v;
    float acc0, acc1;
    v = xr[0 * 32 + lane]; acc0 = a0 * v.x;             acc1 = a0 * v.y;
    v = xr[1 * 32 + lane]; acc0 = fmaf(a1, v.x, acc0);  acc1 = fmaf(a1, v.y, acc1);
    v = xr[2 * 32 + lane]; acc0 = fmaf(a2, v.x, acc0);  acc1 = fmaf(a2, v.y, acc1);
    v = xr[3 * 32 + lane]; acc0 = fmaf(a3, v.x, acc0);  acc1 = fmaf(a3, v.y, acc1);
    atomicAdd(&outy[dst * CC + lane * 2 + 0], acc0);
    atomicAdd(&outy[dst * CC + lane * 2 + 1], acc1);
}

// GraphNorm: one block per group (batch_ptr sorted -> contiguous node ranges).
// t = out_raw/H + bias; mean/var per (group,channel); y = relu(w*(t-mean*sc)*rstd + b2).
__global__ void k_gn(const int* __restrict__ batch_ptr,
                     const float* __restrict__ bias,
                     const float* __restrict__ gnw,
                     const float* __restrict__ gnb,
                     const float* __restrict__ gnsc,
                     float* __restrict__ outy) {
    int g = blockIdx.x;
    __shared__ int s_lo, s_hi;
    if (threadIdx.x == 0) {
        int lo = 0, hi = NN;
        while (lo < hi) { int m = (lo + hi) >> 1; if (batch_ptr[m] < g) lo = m + 1; else hi = m; }
        s_lo = lo;
        int lo2 = lo, hi2 = NN;
        while (lo2 < hi2) { int m = (lo2 + hi2) >> 1; if (batch_ptr[m] < g + 1) lo2 = m + 1; else hi2 = m; }
        s_hi = lo2;
    }
    __syncthreads();
    int lo = s_lo, hi = s_hi;
    float cnt = (float)max(hi - lo, 1);
    int ch = threadIdx.x & 63;
    int ro = threadIdx.x >> 6;  // 0..3
    float b = bias[ch], w = gnw[ch], gb = gnb[ch], sc = gnsc[ch];
    __shared__ float red[256];
    __shared__ float s_ms[64], s_rs[64];

    // phase 1: mean
    float s = 0.0f;
    for (int r = lo + ro; r < hi; r += 4) s += outy[r * CC + ch];
    red[threadIdx.x] = s;
    __syncthreads();
    if (threadIdx.x < 64) {
        float m = red[threadIdx.x] + red[threadIdx.x + 64] + red[threadIdx.x + 128] + red[threadIdx.x + 192];
        float mean = 0.25f * m / cnt + b;   // mean of (raw/4 + bias)
        s_ms[threadIdx.x] = mean * sc;
    }
    __syncthreads();
    float ms = s_ms[ch];

    // phase 2: var
    s = 0.0f;
    for (int r = lo + ro; r < hi; r += 4) {
        float t = fmaf(outy[r * CC + ch], 0.25f, b) - ms;
        s += t * t;
    }
    red[threadIdx.x] = s;
    __syncthreads();
    if (threadIdx.x < 64) {
        float v = (red[threadIdx.x] + red[threadIdx.x + 64] + red[threadIdx.x + 128] + red[threadIdx.x + 192]) / cnt;
        s_rs[threadIdx.x] = rsqrtf(v + GN_EPS);
    }
    __syncthreads();
    float rs = s_rs[ch];

    // phase 3: normalize + affine + relu (in place)
    for (int r = lo + ro; r < hi; r += 4) {
        float t = (fmaf(outy[r * CC + ch], 0.25f, b) - ms) * rs;
        float y = fmaf(w, t, gb);
        outy[r * CC + ch] = fmaxf(y, 0.0f);
    }
}

// ---------------- launch ----------------
extern "C" void kernel_launch(void* const* d_in, const int* in_sizes, int n_in,
                              void* d_out, int out_size) {
    const float* node      = (const float*)d_in[0];
    const int*   ei        = (const int*)d_in[1];
    const float* edge_attr = (const float*)d_in[2];
    const int*   batch_ptr = (const int*)d_in[3];
    const float* W         = (const float*)d_in[4];
    const float* W_edge    = (const float*)d_in[5];
    const float* att_src   = (const float*)d_in[6];
    const float* att_dst   = (const float*)d_in[7];
    const float* att_edge  = (const float*)d_in[8];
    const float* bias      = (const float*)d_in[9];
    const float* gnw       = (const float*)d_in[10];
    const float* gnb       = (const float*)d_in[11];
    const float* gnsc      = (const float*)d_in[12];

    float* outy = (float*)d_out;               // y region [N*C]
    float* att  = (float*)d_out + (size_t)NN * CC;  // att region [E*H]

    k_init<<<1024, 256>>>(outy);
    k_vedge<<<1, 64>>>(W_edge, att_edge);
    k_proj<<<(NN + PROJ_ROWS - 1) / PROJ_ROWS, 256>>>(node, W);
    k_attnodes<<<(NN * HH + 7) / 8, 256>>>(att_src, att_dst);
    k_edgeA<<<(EE + 255) / 256, 256>>>(ei, edge_attr, att);
    k_edgeB<<<(EE + 255) / 256, 256>>>(ei, att);
    k_edgeC<<<(EE + 7) / 8, 256>>>(ei, att, outy);
    k_gn<<<GG, 256>>>(batch_ptr, bias, gnw, gnb, gnsc, outy);
}